// round 2
// baseline (speedup 1.0000x reference)
#include <cuda_runtime.h>
#include <stdint.h>

#define NUM_BINS 256
#define NCH 48                       // B*C = 16*3
#define NPIX (1024 * 1024)           // H*W per channel
#define N16 (NPIX / 16)              // 65536 groups of 16 pixels

// Scratch (device globals — allocation-free, zero-initialized at module load)
__device__ int           g_hist[NCH * NUM_BINS];
__device__ float         g_cdf[NCH * NUM_BINS];
__device__ unsigned char g_bins[(size_t)NCH * NPIX];   // 48 MiB

__device__ __forceinline__ int quant(float v) {
    int q = (int)(fminf(fmaxf(v, 0.0f), 1.0f) * 255.0f);
    return min(max(q, 0), 255);
}

// ---------------------------------------------------------------------------
// Kernel 1: per-channel histogram + packed quantized-bin store
//   grid = (32, NCH), block = 256; each thread handles 16 pixels/iter
// ---------------------------------------------------------------------------
__global__ void __launch_bounds__(256) hist_kernel(const float* __restrict__ x) {
    __shared__ int sh[NUM_BINS];
    const int c = blockIdx.y;

    sh[threadIdx.x] = 0;
    __syncthreads();

    const float4* xc = reinterpret_cast<const float4*>(x + (size_t)c * NPIX);
    uint4*        bc = reinterpret_cast<uint4*>(g_bins + (size_t)c * NPIX);

    const int stride = gridDim.x * blockDim.x;
    for (int i = blockIdx.x * blockDim.x + threadIdx.x; i < N16; i += stride) {
        // 64B of input -> 16 bins -> one 16B store
        float4 v0 = xc[i * 4 + 0];
        float4 v1 = xc[i * 4 + 1];
        float4 v2 = xc[i * 4 + 2];
        float4 v3 = xc[i * 4 + 3];

        int q00 = quant(v0.x), q01 = quant(v0.y), q02 = quant(v0.z), q03 = quant(v0.w);
        int q10 = quant(v1.x), q11 = quant(v1.y), q12 = quant(v1.z), q13 = quant(v1.w);
        int q20 = quant(v2.x), q21 = quant(v2.y), q22 = quant(v2.z), q23 = quant(v2.w);
        int q30 = quant(v3.x), q31 = quant(v3.y), q32 = quant(v3.z), q33 = quant(v3.w);

        atomicAdd(&sh[q00], 1); atomicAdd(&sh[q01], 1);
        atomicAdd(&sh[q02], 1); atomicAdd(&sh[q03], 1);
        atomicAdd(&sh[q10], 1); atomicAdd(&sh[q11], 1);
        atomicAdd(&sh[q12], 1); atomicAdd(&sh[q13], 1);
        atomicAdd(&sh[q20], 1); atomicAdd(&sh[q21], 1);
        atomicAdd(&sh[q22], 1); atomicAdd(&sh[q23], 1);
        atomicAdd(&sh[q30], 1); atomicAdd(&sh[q31], 1);
        atomicAdd(&sh[q32], 1); atomicAdd(&sh[q33], 1);

        uint4 p;
        p.x = (unsigned)q00 | ((unsigned)q01 << 8) | ((unsigned)q02 << 16) | ((unsigned)q03 << 24);
        p.y = (unsigned)q10 | ((unsigned)q11 << 8) | ((unsigned)q12 << 16) | ((unsigned)q13 << 24);
        p.z = (unsigned)q20 | ((unsigned)q21 << 8) | ((unsigned)q22 << 16) | ((unsigned)q23 << 24);
        p.w = (unsigned)q30 | ((unsigned)q31 << 8) | ((unsigned)q32 << 16) | ((unsigned)q33 << 24);
        bc[i] = p;
    }
    __syncthreads();

    int v = sh[threadIdx.x];
    if (v) atomicAdd(&g_hist[c * NUM_BINS + threadIdx.x], v);
}

// ---------------------------------------------------------------------------
// Kernel 2: CDF scan + normalize, then re-zero g_hist for the next replay
//   grid = NCH, block = 256
// ---------------------------------------------------------------------------
__global__ void cdf_kernel() {
    __shared__ float s[NUM_BINS];
    const int c = blockIdx.x;
    const int t = threadIdx.x;

    s[t] = (float)g_hist[c * NUM_BINS + t];
    g_hist[c * NUM_BINS + t] = 0;       // restore zero-invariant for next call
    __syncthreads();

    #pragma unroll
    for (int off = 1; off < NUM_BINS; off <<= 1) {
        float v = (t >= off) ? s[t - off] : 0.0f;
        __syncthreads();
        s[t] += v;
        __syncthreads();
    }

    float total = s[NUM_BINS - 1];
    g_cdf[c * NUM_BINS + t] = s[t] / fmaxf(total, 1.0f);
}

// ---------------------------------------------------------------------------
// Kernel 3: remap via bank-conflict-free replicated LUT (32 copies)
//   grid = (32, NCH), block = 256; each thread handles 16 pixels/iter
// ---------------------------------------------------------------------------
__global__ void __launch_bounds__(256) remap_kernel(float* __restrict__ out) {
    __shared__ float srep[NUM_BINS * 32];       // 32 KB: srep[bin*32 + lane]
    const int c    = blockIdx.y;
    const int lane = threadIdx.x & 31;

    {
        float v = g_cdf[c * NUM_BINS + threadIdx.x];
        #pragma unroll
        for (int l = 0; l < 32; l++)
            srep[threadIdx.x * 32 + l] = v;
    }
    __syncthreads();

    const uint4* bc = reinterpret_cast<const uint4*>(g_bins + (size_t)c * NPIX);
    float4*      oc = reinterpret_cast<float4*>(out + (size_t)c * NPIX);

    const int stride = gridDim.x * blockDim.x;
    for (int i = blockIdx.x * blockDim.x + threadIdx.x; i < N16; i += stride) {
        uint4 p = bc[i];

        float4 r0, r1, r2, r3;
        r0.x = srep[((p.x      ) & 0xFF) * 32 + lane];
        r0.y = srep[((p.x >>  8) & 0xFF) * 32 + lane];
        r0.z = srep[((p.x >> 16) & 0xFF) * 32 + lane];
        r0.w = srep[((p.x >> 24)       ) * 32 + lane];
        r1.x = srep[((p.y      ) & 0xFF) * 32 + lane];
        r1.y = srep[((p.y >>  8) & 0xFF) * 32 + lane];
        r1.z = srep[((p.y >> 16) & 0xFF) * 32 + lane];
        r1.w = srep[((p.y >> 24)       ) * 32 + lane];
        r2.x = srep[((p.z      ) & 0xFF) * 32 + lane];
        r2.y = srep[((p.z >>  8) & 0xFF) * 32 + lane];
        r2.z = srep[((p.z >> 16) & 0xFF) * 32 + lane];
        r2.w = srep[((p.z >> 24)       ) * 32 + lane];
        r3.x = srep[((p.w      ) & 0xFF) * 32 + lane];
        r3.y = srep[((p.w >>  8) & 0xFF) * 32 + lane];
        r3.z = srep[((p.w >> 16) & 0xFF) * 32 + lane];
        r3.w = srep[((p.w >> 24)       ) * 32 + lane];

        oc[i * 4 + 0] = r0;
        oc[i * 4 + 1] = r1;
        oc[i * 4 + 2] = r2;
        oc[i * 4 + 3] = r3;
    }
}

// ---------------------------------------------------------------------------
extern "C" void kernel_launch(void* const* d_in, const int* in_sizes, int n_in,
                              void* d_out, int out_size) {
    const float* x   = (const float*)d_in[0];
    float*       out = (float*)d_out;

    dim3 grid(32, NCH);           // 1536 CTAs
    hist_kernel<<<grid, 256>>>(x);
    cdf_kernel<<<NCH, 256>>>();
    remap_kernel<<<grid, 256>>>(out);
}

// round 3
// speedup vs baseline: 1.1559x; 1.1559x over previous
#include <cuda_runtime.h>
#include <stdint.h>

#define NUM_BINS 256
#define NCH 48                       // B*C = 16*3
#define NPIX (1024 * 1024)           // H*W per channel
#define N4 (NPIX / 4)                // 262144 uchar4/float4 groups per channel
#define BLK_PER_CH 32
#define THREADS 256
#define CH_THREADS (BLK_PER_CH * THREADS)   // 8192
#define ITERS (N4 / CH_THREADS)             // exactly 32

// Scratch (device globals — allocation-free, zero-initialized at module load)
__device__ int           g_hist[NCH * NUM_BINS];
__device__ float         g_cdf[NCH * NUM_BINS];
__device__ unsigned char g_bins[(size_t)NCH * NPIX];   // 48 MiB

__device__ __forceinline__ int quant(float v) {
    int q = (int)(fminf(fmaxf(v, 0.0f), 1.0f) * 255.0f);
    return min(max(q, 0), 255);
}

// ---------------------------------------------------------------------------
// Kernel 1: per-channel histogram (per-warp privatized) + quantized-bin store
//   grid = (BLK_PER_CH, NCH), block = 256
// ---------------------------------------------------------------------------
__global__ void __launch_bounds__(THREADS) hist_kernel(const float* __restrict__ x) {
    __shared__ int sh[8 * NUM_BINS];            // 8 warps x 256 bins = 8 KB
    const int c    = blockIdx.y;
    const int warp = threadIdx.x >> 5;
    int* swh = &sh[warp * NUM_BINS];

    #pragma unroll
    for (int i = threadIdx.x; i < 8 * NUM_BINS; i += THREADS) sh[i] = 0;
    __syncthreads();

    const float4* xc = reinterpret_cast<const float4*>(x + (size_t)c * NPIX);
    uchar4*       bc = reinterpret_cast<uchar4*>(g_bins + (size_t)c * NPIX);

    const int base = blockIdx.x * THREADS + threadIdx.x;
    #pragma unroll 2
    for (int k = 0; k < ITERS; k++) {
        int i = base + k * CH_THREADS;
        float4 v = xc[i];
        int q0 = quant(v.x), q1 = quant(v.y), q2 = quant(v.z), q3 = quant(v.w);

        atomicAdd(&swh[q0], 1);
        atomicAdd(&swh[q1], 1);
        atomicAdd(&swh[q2], 1);
        atomicAdd(&swh[q3], 1);

        bc[i] = make_uchar4((unsigned char)q0, (unsigned char)q1,
                            (unsigned char)q2, (unsigned char)q3);
    }
    __syncthreads();

    // reduce 8 warp-copies and flush once per bin
    int bin = threadIdx.x;
    int sum = 0;
    #pragma unroll
    for (int w = 0; w < 8; w++) sum += sh[w * NUM_BINS + bin];
    if (sum) atomicAdd(&g_hist[c * NUM_BINS + bin], sum);
}

// ---------------------------------------------------------------------------
// Kernel 2: CDF scan + normalize, then re-zero g_hist for the next replay
//   grid = NCH, block = 256
// ---------------------------------------------------------------------------
__global__ void cdf_kernel() {
    __shared__ float s[NUM_BINS];
    const int c = blockIdx.x;
    const int t = threadIdx.x;

    s[t] = (float)g_hist[c * NUM_BINS + t];
    g_hist[c * NUM_BINS + t] = 0;       // restore zero-invariant for next call
    __syncthreads();

    #pragma unroll
    for (int off = 1; off < NUM_BINS; off <<= 1) {
        float v = (t >= off) ? s[t - off] : 0.0f;
        __syncthreads();
        s[t] += v;
        __syncthreads();
    }

    float total = s[NUM_BINS - 1];
    g_cdf[c * NUM_BINS + t] = s[t] / fmaxf(total, 1.0f);
}

// ---------------------------------------------------------------------------
// Kernel 3: remap via 1 KB LUT; exact trip count, unroll 4 for MLP
//   grid = (BLK_PER_CH, NCH), block = 256
// ---------------------------------------------------------------------------
__global__ void __launch_bounds__(THREADS) remap_kernel(float* __restrict__ out) {
    __shared__ float scdf[NUM_BINS];
    const int c = blockIdx.y;

    scdf[threadIdx.x] = g_cdf[c * NUM_BINS + threadIdx.x];
    __syncthreads();

    const uchar4* bc = reinterpret_cast<const uchar4*>(g_bins + (size_t)c * NPIX);
    float4*       oc = reinterpret_cast<float4*>(out + (size_t)c * NPIX);

    const int base = blockIdx.x * THREADS + threadIdx.x;
    #pragma unroll 4
    for (int k = 0; k < ITERS; k++) {
        int i = base + k * CH_THREADS;
        uchar4 q = bc[i];
        float4 r;
        r.x = scdf[q.x];
        r.y = scdf[q.y];
        r.z = scdf[q.z];
        r.w = scdf[q.w];
        oc[i] = r;
    }
}

// ---------------------------------------------------------------------------
extern "C" void kernel_launch(void* const* d_in, const int* in_sizes, int n_in,
                              void* d_out, int out_size) {
    const float* x   = (const float*)d_in[0];
    float*       out = (float*)d_out;

    dim3 grid(BLK_PER_CH, NCH);     // 1536 CTAs
    hist_kernel<<<grid, THREADS>>>(x);
    cdf_kernel<<<NCH, NUM_BINS>>>();
    remap_kernel<<<grid, THREADS>>>(out);
}

// round 4
// speedup vs baseline: 1.2770x; 1.1048x over previous
#include <cuda_runtime.h>
#include <stdint.h>

#define NUM_BINS 256
#define NCH 48                       // B*C = 16*3
#define NPIX (1024 * 1024)           // H*W per channel
#define N4 (NPIX / 4)                // 262144 uchar4/float4 groups per channel
#define NHALF (N4 / 2)               // 131072
#define BLK_PER_CH 32
#define THREADS 256
#define CH_THREADS (BLK_PER_CH * THREADS)   // 8192
#define ITERS (N4 / CH_THREADS)             // exactly 32

// Scratch (device globals — allocation-free, zero-initialized at module load)
__device__ int           g_hist[NCH * NUM_BINS];
__device__ float         g_cdf[NCH * NUM_BINS];
__device__ unsigned char g_bins[(size_t)NCH * NPIX];   // 48 MiB

__device__ __forceinline__ int quant(float v) {
    int q = (int)(fminf(fmaxf(v, 0.0f), 1.0f) * 255.0f);
    return min(max(q, 0), 255);
}

// ---------------------------------------------------------------------------
// Kernel 1: per-channel histogram (per-warp privatized) + quantized-bin store
//   grid = (BLK_PER_CH, NCH), block = 256        [unchanged from R3: 42 µs]
// ---------------------------------------------------------------------------
__global__ void __launch_bounds__(THREADS) hist_kernel(const float* __restrict__ x) {
    __shared__ int sh[8 * NUM_BINS];            // 8 warps x 256 bins = 8 KB
    const int c    = blockIdx.y;
    const int warp = threadIdx.x >> 5;
    int* swh = &sh[warp * NUM_BINS];

    #pragma unroll
    for (int i = threadIdx.x; i < 8 * NUM_BINS; i += THREADS) sh[i] = 0;
    __syncthreads();

    const float4* xc = reinterpret_cast<const float4*>(x + (size_t)c * NPIX);
    uchar4*       bc = reinterpret_cast<uchar4*>(g_bins + (size_t)c * NPIX);

    const int base = blockIdx.x * THREADS + threadIdx.x;
    #pragma unroll 2
    for (int k = 0; k < ITERS; k++) {
        int i = base + k * CH_THREADS;
        float4 v = xc[i];
        int q0 = quant(v.x), q1 = quant(v.y), q2 = quant(v.z), q3 = quant(v.w);

        atomicAdd(&swh[q0], 1);
        atomicAdd(&swh[q1], 1);
        atomicAdd(&swh[q2], 1);
        atomicAdd(&swh[q3], 1);

        bc[i] = make_uchar4((unsigned char)q0, (unsigned char)q1,
                            (unsigned char)q2, (unsigned char)q3);
    }
    __syncthreads();

    int bin = threadIdx.x;
    int sum = 0;
    #pragma unroll
    for (int w = 0; w < 8; w++) sum += sh[w * NUM_BINS + bin];
    if (sum) atomicAdd(&g_hist[c * NUM_BINS + bin], sum);
}

// ---------------------------------------------------------------------------
// Kernel 2: CDF scan + normalize, then re-zero g_hist for the next replay
//   grid = NCH, block = 256                       [unchanged]
// ---------------------------------------------------------------------------
__global__ void cdf_kernel() {
    __shared__ float s[NUM_BINS];
    const int c = blockIdx.x;
    const int t = threadIdx.x;

    s[t] = (float)g_hist[c * NUM_BINS + t];
    g_hist[c * NUM_BINS + t] = 0;       // restore zero-invariant for next call
    __syncthreads();

    #pragma unroll
    for (int off = 1; off < NUM_BINS; off <<= 1) {
        float v = (t >= off) ? s[t - off] : 0.0f;
        __syncthreads();
        s[t] += v;
        __syncthreads();
    }

    float total = s[NUM_BINS - 1];
    g_cdf[c * NUM_BINS + t] = s[t] / fmaxf(total, 1.0f);
}

// ---------------------------------------------------------------------------
// Kernel 3: remap — R1 shape (grid-stride, 1 KB LUT, uchar4) but each thread
//           drives TWO independent streams at stride NHALF for MLP=2.
//   grid = (24, NCH), block = 256
// ---------------------------------------------------------------------------
__global__ void __launch_bounds__(THREADS) remap_kernel(float* __restrict__ out) {
    __shared__ float scdf[NUM_BINS];
    const int c = blockIdx.y;

    scdf[threadIdx.x] = g_cdf[c * NUM_BINS + threadIdx.x];
    __syncthreads();

    const uchar4* bc = reinterpret_cast<const uchar4*>(g_bins + (size_t)c * NPIX);
    float4*       oc = reinterpret_cast<float4*>(out + (size_t)c * NPIX);

    const int stride = gridDim.x * blockDim.x;          // 6144
    for (int i = blockIdx.x * blockDim.x + threadIdx.x; i < NHALF; i += stride) {
        uchar4 qa = bc[i];
        uchar4 qb = bc[i + NHALF];

        float4 ra, rb;
        ra.x = scdf[qa.x];
        ra.y = scdf[qa.y];
        ra.z = scdf[qa.z];
        ra.w = scdf[qa.w];
        rb.x = scdf[qb.x];
        rb.y = scdf[qb.y];
        rb.z = scdf[qb.z];
        rb.w = scdf[qb.w];

        oc[i]         = ra;
        oc[i + NHALF] = rb;
    }
}

// ---------------------------------------------------------------------------
extern "C" void kernel_launch(void* const* d_in, const int* in_sizes, int n_in,
                              void* d_out, int out_size) {
    const float* x   = (const float*)d_in[0];
    float*       out = (float*)d_out;

    dim3 gridH(BLK_PER_CH, NCH);    // 1536 CTAs
    hist_kernel<<<gridH, THREADS>>>(x);
    cdf_kernel<<<NCH, NUM_BINS>>>();
    dim3 gridR(24, NCH);            // 1152 CTAs (R1 shape)
    remap_kernel<<<gridR, THREADS>>>(out);
}